// round 15
// baseline (speedup 1.0000x reference)
#include <cuda_runtime.h>
#include <cuda_fp16.h>
#include <mma.h>
#include <cstdint>

using namespace nvcuda;

// ---------------- problem-size constants (padded maxima for static scratch) ---
constexpr int NMAX = 50048;        // >= 50000 nodes
constexpr int SCAN_BLOCKS = 52;
constexpr int NPAD = SCAN_BLOCKS * 1024;   // 53248 (scan coverage)
constexpr int EMAX = 1600000;      // edges
constexpr int HID  = 128;          // hidden width (both layers use 128 cols)

// ---------------- static device scratch (no allocations allowed) -------------
// g_deg tail [NPAD, NPAD+64) doubles as scan block-sum flags (memset covers it)
__device__ int    g_deg[NPAD + 64];
__device__ float  g_dinv[NPAD];
__device__ int    g_rowstart[NPAD + 4];
__device__ int    g_rank[EMAX];
__device__ int    g_csr_src[EMAX];
__device__ __half g_Hs1[(size_t)NMAX * HID];  // x@W1, then prescaled by dinv (fp16)
__device__ __half g_hh[(size_t)NMAX * HID];   // hidden activations fp16 (GEMM2 A)
__device__ __half g_Hs2[(size_t)NMAX * HID];  // dinv-scaled h@[Wmu|Wls], fp16
__device__ __half g_W1h[256 * HID];           // W1 fp16
__device__ __half g_W2h[HID * HID];           // concat(W_mu, W_ls) fp16

// ---------------- CSR build ---------------------------------------------------
// 8 edges per thread: 8 independent atomic chains for MLP
__global__ void k_hist_rank8(const int* __restrict__ dst, int E) {
    int i = blockIdx.x * blockDim.x + threadIdx.x;
    int base = i * 8;
    if (base + 8 <= E) {
        int4 da = *(const int4*)&dst[base];
        int4 db = *(const int4*)&dst[base + 4];
        int r0 = atomicAdd(&g_deg[da.x], 1);
        int r1 = atomicAdd(&g_deg[da.y], 1);
        int r2 = atomicAdd(&g_deg[da.z], 1);
        int r3 = atomicAdd(&g_deg[da.w], 1);
        int r4 = atomicAdd(&g_deg[db.x], 1);
        int r5 = atomicAdd(&g_deg[db.y], 1);
        int r6 = atomicAdd(&g_deg[db.z], 1);
        int r7 = atomicAdd(&g_deg[db.w], 1);
        *(int4*)&g_rank[base]     = make_int4(r0, r1, r2, r3);
        *(int4*)&g_rank[base + 4] = make_int4(r4, r5, r6, r7);
    } else {
        for (int j = base; j < E; j++) g_rank[j] = atomicAdd(&g_deg[dst[j]], 1);
    }
}

// grid-wide exclusive scan, single pass: 52 blocks x 1024 threads, 1 elem/thread.
__global__ __launch_bounds__(1024) void k_scan2() {
    __shared__ int sh_scan[32];
    __shared__ int sh_red[32];
    __shared__ int s_total, s_off;
    const int b = blockIdx.x, t = threadIdx.x;
    const int idx = b * 1024 + t;
    const int d = g_deg[idx];
    const int lane = t & 31, wid = t >> 5;

    int v = d;
    #pragma unroll
    for (int s = 1; s < 32; s <<= 1) {
        int n = __shfl_up_sync(0xffffffff, v, s);
        if (lane >= s) v += n;
    }
    if (lane == 31) sh_scan[wid] = v;
    __syncthreads();
    if (wid == 0) {
        int w = sh_scan[lane];
        #pragma unroll
        for (int s = 1; s < 32; s <<= 1) {
            int n = __shfl_up_sync(0xffffffff, w, s);
            if (lane >= s) w += n;
        }
        sh_scan[lane] = w;
    }
    __syncthreads();
    int incl = v + (wid > 0 ? sh_scan[wid - 1] : 0);
    int excl = incl - d;
    if (t == 1023) s_total = incl;
    __syncthreads();

    if (t == 0) {
        __threadfence();
        atomicExch(&g_deg[NPAD + b], s_total + 1);
    }

    int p = 0;
    if (t < b) {
        int vv;
        while ((vv = atomicAdd(&g_deg[NPAD + t], 0)) == 0) { __nanosleep(50); }
        p = vv - 1;
    }
    #pragma unroll
    for (int s = 16; s > 0; s >>= 1) p += __shfl_down_sync(0xffffffff, p, s);
    if (lane == 0) sh_red[wid] = p;
    __syncthreads();
    if (wid == 0) {
        int w = sh_red[lane];
        #pragma unroll
        for (int s = 16; s > 0; s >>= 1) w += __shfl_down_sync(0xffffffff, w, s);
        if (lane == 0) s_off = w;
    }
    __syncthreads();

    g_rowstart[idx] = excl + s_off;
    g_dinv[idx] = rsqrtf((float)(d + 1));   // +1 self-loop (pad rows -> 1, unused)
}

// 8 edges per thread: 8 independent load->load->store chains
__global__ void k_scatter8(const int* __restrict__ src, const int* __restrict__ dst, int E) {
    int i = blockIdx.x * blockDim.x + threadIdx.x;
    int base = i * 8;
    if (base + 8 <= E) {
        int4 da = *(const int4*)&dst[base];
        int4 db = *(const int4*)&dst[base + 4];
        int4 ra = *(const int4*)&g_rank[base];
        int4 rb = *(const int4*)&g_rank[base + 4];
        int4 sa = *(const int4*)&src[base];
        int4 sb = *(const int4*)&src[base + 4];
        int p0 = g_rowstart[da.x] + ra.x;
        int p1 = g_rowstart[da.y] + ra.y;
        int p2 = g_rowstart[da.z] + ra.z;
        int p3 = g_rowstart[da.w] + ra.w;
        int p4 = g_rowstart[db.x] + rb.x;
        int p5 = g_rowstart[db.y] + rb.y;
        int p6 = g_rowstart[db.z] + rb.z;
        int p7 = g_rowstart[db.w] + rb.w;
        g_csr_src[p0] = sa.x;
        g_csr_src[p1] = sa.y;
        g_csr_src[p2] = sa.z;
        g_csr_src[p3] = sa.w;
        g_csr_src[p4] = sb.x;
        g_csr_src[p5] = sb.y;
        g_csr_src[p6] = sb.z;
        g_csr_src[p7] = sb.w;
    } else {
        for (int j = base; j < E; j++)
            g_csr_src[g_rowstart[dst[j]] + g_rank[j]] = src[j];
    }
}

// fused weight conversion: W1 (256x128) and [Wmu|Wls] (128x128) to fp16
__global__ void k_w12h(const float* __restrict__ W1, const float* __restrict__ Wmu,
                       const float* __restrict__ Wls) {
    int i = blockIdx.x * blockDim.x + threadIdx.x;
    if (i < 256 * HID) {
        g_W1h[i] = __float2half_rn(W1[i]);
    } else if (i < 256 * HID + HID * HID) {
        int j = i - 256 * HID;
        int k = j >> 7, c = j & 127;
        g_W2h[j] = __float2half_rn((c < 64) ? Wmu[k * 64 + c] : Wls[k * 64 + (c - 64)]);
    }
}

// in-place row prescale: Hs1[r,:] *= dinv[r]  (uint2 = 4 halves per thread)
__global__ void k_prescale(int total) {
    int i = blockIdx.x * blockDim.x + threadIdx.x;
    if (i >= total) return;
    int row = i >> 5;                         // warp-uniform
    float w = g_dinv[row];
    uint2 u = ((const uint2*)g_Hs1)[i];
    float2 lo = __half22float2(*reinterpret_cast<__half2*>(&u.x));
    float2 hi = __half22float2(*reinterpret_cast<__half2*>(&u.y));
    __half2 h0 = __float22half2_rn(make_float2(lo.x * w, lo.y * w));
    __half2 h1 = __float22half2_rn(make_float2(hi.x * w, hi.y * w));
    uint2 o;
    o.x = *reinterpret_cast<unsigned*>(&h0);
    o.y = *reinterpret_cast<unsigned*>(&h1);
    ((uint2*)g_Hs1)[i] = o;
}

// ---------------- helpers ------------------------------------------------------
__device__ __forceinline__ void acc_h4(float4& a, uint2 u) {
    float2 lo = __half22float2(*reinterpret_cast<__half2*>(&u.x));
    float2 hi = __half22float2(*reinterpret_cast<__half2*>(&u.y));
    a.x += lo.x; a.y += lo.y; a.z += hi.x; a.w += hi.y;
}

// unweighted gather-sum (rows already dinv-prescaled); MLP-8 main loop
__device__ __forceinline__ float4 gather_sum(const uint2* __restrict__ Hs4,
                                             int node, int lane) {
    uint2 self = Hs4[(size_t)node * 32 + lane];
    float4 acc = make_float4(0.f, 0.f, 0.f, 0.f);
    acc_h4(acc, self);

    int e = g_rowstart[node];
    const int end = g_rowstart[node + 1];
    for (; e + 8 <= end; e += 8) {
        int s0 = g_csr_src[e + 0], s1 = g_csr_src[e + 1];
        int s2 = g_csr_src[e + 2], s3 = g_csr_src[e + 3];
        int s4 = g_csr_src[e + 4], s5 = g_csr_src[e + 5];
        int s6 = g_csr_src[e + 6], s7 = g_csr_src[e + 7];
        uint2 u0 = __ldg(&Hs4[(size_t)s0 * 32 + lane]);
        uint2 u1 = __ldg(&Hs4[(size_t)s1 * 32 + lane]);
        uint2 u2 = __ldg(&Hs4[(size_t)s2 * 32 + lane]);
        uint2 u3 = __ldg(&Hs4[(size_t)s3 * 32 + lane]);
        uint2 u4 = __ldg(&Hs4[(size_t)s4 * 32 + lane]);
        uint2 u5 = __ldg(&Hs4[(size_t)s5 * 32 + lane]);
        uint2 u6 = __ldg(&Hs4[(size_t)s6 * 32 + lane]);
        uint2 u7 = __ldg(&Hs4[(size_t)s7 * 32 + lane]);
        acc_h4(acc, u0); acc_h4(acc, u1); acc_h4(acc, u2); acc_h4(acc, u3);
        acc_h4(acc, u4); acc_h4(acc, u5); acc_h4(acc, u6); acc_h4(acc, u7);
    }
    for (; e + 2 <= end; e += 2) {
        int s0 = g_csr_src[e + 0], s1 = g_csr_src[e + 1];
        uint2 u0 = __ldg(&Hs4[(size_t)s0 * 32 + lane]);
        uint2 u1 = __ldg(&Hs4[(size_t)s1 * 32 + lane]);
        acc_h4(acc, u0); acc_h4(acc, u1);
    }
    if (e < end) {
        uint2 u = __ldg(&Hs4[(size_t)g_csr_src[e] * 32 + lane]);
        acc_h4(acc, u);
    }
    return acc;
}

// ---------------- aggregation, one warp per node -------------------------------
// P[d,:] = dinv[d] * ( Hs[d,:] + sum_{edges s->d} Hs[s,:] )   (Hs prescaled)
// layer 1 variant: h = relu(P + b1), write fp16; node range [node0, node1)
__global__ __launch_bounds__(256) void k_agg_relu(int node0, int node1,
                                                  const float* __restrict__ b) {
    int warp = node0 + ((blockIdx.x * blockDim.x + threadIdx.x) >> 5);
    int lane = threadIdx.x & 31;
    if (warp >= node1) return;
    float4 acc = gather_sum((const uint2*)g_Hs1, warp, lane);

    float dd = g_dinv[warp];
    int c = lane * 4;
    float4 bb = *(const float4*)&b[c];
    __half2 h0 = __float22half2_rn(make_float2(fmaxf(acc.x * dd + bb.x, 0.f),
                                               fmaxf(acc.y * dd + bb.y, 0.f)));
    __half2 h1 = __float22half2_rn(make_float2(fmaxf(acc.z * dd + bb.z, 0.f),
                                               fmaxf(acc.w * dd + bb.w, 0.f)));
    uint2 pack;
    pack.x = *reinterpret_cast<unsigned*>(&h0);
    pack.y = *reinterpret_cast<unsigned*>(&h1);
    ((uint2*)g_hh)[(size_t)warp * 32 + lane] = pack;
}

// layer 2 variant: split into (mu, logstd) halves with biases, write to output
__global__ __launch_bounds__(256) void k_agg_out(int N, const float* __restrict__ bmu,
                                                 const float* __restrict__ bls,
                                                 float* __restrict__ out) {
    int warp = (blockIdx.x * blockDim.x + threadIdx.x) >> 5;
    int lane = threadIdx.x & 31;
    if (warp >= N) return;
    float4 acc = gather_sum((const uint2*)g_Hs2, warp, lane);

    float dd = g_dinv[warp];
    int c = lane * 4;   // 0..124
    float4 r;
    if (c < 64) {
        float4 bb = *(const float4*)&bmu[c];
        r.x = acc.x * dd + bb.x; r.y = acc.y * dd + bb.y;
        r.z = acc.z * dd + bb.z; r.w = acc.w * dd + bb.w;
        *(float4*)&out[(size_t)warp * 64 + c] = r;
    } else {
        float4 bb = *(const float4*)&bls[c - 64];
        r.x = acc.x * dd + bb.x; r.y = acc.y * dd + bb.y;
        r.z = acc.z * dd + bb.z; r.w = acc.w * dd + bb.w;
        *(float4*)&out[(size_t)N * 64 + (size_t)warp * 64 + (c - 64)] = r;
    }
}

// ---------------- tensor-core GEMM: Hs[row0+.. ,128] = fp16([dinv*](A@B)) ------
// BM=128, BN=128, BK=32. 256 threads = 8 warps in 4x2 grid; warp tile 32x64.
// row0: starting row of this launch's tile range (for chunked pipelining).
template<bool A_IS_HALF, bool SCALE_D>
__global__ __launch_bounds__(256) void k_hgemm(int M, int K, int row0,
                                               const void* __restrict__ Av,
                                               const __half* __restrict__ B,
                                               __half* __restrict__ Hs) {
    constexpr int BM = 128, BN = 128, BK = 32;
    __shared__ __align__(32) __half As[BM][BK + 8];
    __shared__ __align__(32) __half Bs[BK][BN + 8];
    __shared__ __align__(32) float  Cs[8][16][24];

    const int tid = threadIdx.x;
    const int wid = tid >> 5;
    const int lane = tid & 31;
    const int warp_m = wid >> 1;          // 0..3
    const int warp_n = wid & 1;           // 0..1
    const int block_row = row0 + blockIdx.x * BM;

    wmma::fragment<wmma::accumulator, 16, 16, 16, float> facc[2][4];
    #pragma unroll
    for (int i = 0; i < 2; i++)
        #pragma unroll
        for (int j = 0; j < 4; j++) wmma::fill_fragment(facc[i][j], 0.0f);

    for (int k0 = 0; k0 < K; k0 += BK) {
        if (A_IS_HALF) {
            const __half* A = (const __half*)Av;
            #pragma unroll
            for (int i = 0; i < 4; i++) {
                int idx = tid + i * 256;
                int r = idx >> 3, c4 = (idx & 7) * 4;
                int gr = block_row + r;
                uint2 v = make_uint2(0u, 0u);
                if (gr < M) v = *(const uint2*)&A[(size_t)gr * K + k0 + c4];
                *(uint2*)&As[r][c4] = v;
            }
        } else {
            const float* A = (const float*)Av;
            #pragma unroll
            for (int i = 0; i < 4; i++) {
                int idx = tid + i * 256;
                int r = idx >> 3, c4 = (idx & 7) * 4;
                int gr = block_row + r;
                float4 v = make_float4(0.f, 0.f, 0.f, 0.f);
                if (gr < M) v = *(const float4*)&A[(size_t)gr * K + k0 + c4];
                __half2 h0 = __float22half2_rn(make_float2(v.x, v.y));
                __half2 h1 = __float22half2_rn(make_float2(v.z, v.w));
                uint2 pack;
                pack.x = *reinterpret_cast<unsigned*>(&h0);
                pack.y = *reinterpret_cast<unsigned*>(&h1);
                *(uint2*)&As[r][c4] = pack;
            }
        }
        #pragma unroll
        for (int i = 0; i < 4; i++) {
            int idx = tid + i * 256;
            int r = idx >> 5, c4 = (idx & 31) * 4;
            *(uint2*)&Bs[r][c4] = *(const uint2*)&B[(size_t)(k0 + r) * BN + c4];
        }
        __syncthreads();

        #pragma unroll
        for (int kk = 0; kk < BK; kk += 16) {
            wmma::fragment<wmma::matrix_a, 16, 16, 16, __half, wmma::row_major> fa[2];
            wmma::fragment<wmma::matrix_b, 16, 16, 16, __half, wmma::row_major> fb[4];
            #pragma unroll
            for (int i = 0; i < 2; i++)
                wmma::load_matrix_sync(fa[i], &As[warp_m * 32 + i * 16][kk], BK + 8);
            #pragma unroll
            for (int j = 0; j < 4; j++)
                wmma::load_matrix_sync(fb[j], &Bs[kk][warp_n * 64 + j * 16], BN + 8);
            #pragma unroll
            for (int i = 0; i < 2; i++)
                #pragma unroll
                for (int j = 0; j < 4; j++)
                    wmma::mma_sync(facc[i][j], fa[i], fb[j], facc[i][j]);
        }
        __syncthreads();
    }

    // ---- epilogue: optional row scale by dinv, convert fp16, store ----
    #pragma unroll
    for (int i = 0; i < 2; i++) {
        #pragma unroll
        for (int j = 0; j < 4; j++) {
            wmma::store_matrix_sync(&Cs[wid][0][0], facc[i][j], 24, wmma::mem_row_major);
            __syncwarp();
            int r = lane >> 1;
            int gr = block_row + warp_m * 32 + i * 16 + r;
            int col = warp_n * 64 + j * 16 + (lane & 1) * 8;
            if (gr < M) {
                float di = SCALE_D ? g_dinv[gr] : 1.0f;
                float4 v0 = *(float4*)&Cs[wid][r][(lane & 1) * 8];
                float4 v1 = *(float4*)&Cs[wid][r][(lane & 1) * 8 + 4];
                __half2 h0 = __float22half2_rn(make_float2(v0.x * di, v0.y * di));
                __half2 h1 = __float22half2_rn(make_float2(v0.z * di, v0.w * di));
                __half2 h2 = __float22half2_rn(make_float2(v1.x * di, v1.y * di));
                __half2 h3 = __float22half2_rn(make_float2(v1.z * di, v1.w * di));
                uint4 pack;
                pack.x = *reinterpret_cast<unsigned*>(&h0);
                pack.y = *reinterpret_cast<unsigned*>(&h1);
                pack.z = *reinterpret_cast<unsigned*>(&h2);
                pack.w = *reinterpret_cast<unsigned*>(&h3);
                *(uint4*)&Hs[(size_t)gr * BN + col] = pack;
            }
            __syncwarp();
        }
    }
}

// ---------------- launch ------------------------------------------------------
extern "C" void kernel_launch(void* const* d_in, const int* in_sizes, int n_in,
                              void* d_out, int out_size) {
    const float* x  = (const float*)d_in[0];
    const int*   ei = (const int*)d_in[1];
    int base = (n_in >= 9 && in_sizes[2] == 1) ? 3 : 2;
    const float* W1  = (const float*)d_in[base + 0];
    const float* b1  = (const float*)d_in[base + 1];
    const float* Wmu = (const float*)d_in[base + 2];
    const float* bmu = (const float*)d_in[base + 3];
    const float* Wls = (const float*)d_in[base + 4];
    const float* bls = (const float*)d_in[base + 5];
    float* out = (float*)d_out;

    const int N = in_sizes[0] / 256;   // 50000
    const int E = in_sizes[1] / 2;     // 1600000
    const int* src = ei;
    const int* dst = ei + E;

    __half *pHs1, *pHs2, *phh, *pW1h, *pW2h;
    int* pdeg;
    cudaGetSymbolAddress((void**)&pHs1, g_Hs1);
    cudaGetSymbolAddress((void**)&phh,  g_hh);
    cudaGetSymbolAddress((void**)&pHs2, g_Hs2);
    cudaGetSymbolAddress((void**)&pW1h, g_W1h);
    cudaGetSymbolAddress((void**)&pW2h, g_W2h);
    cudaGetSymbolAddress((void**)&pdeg, g_deg);

    // one-time side-stream + events (host resources, not device memory)
    static cudaStream_t s2 = nullptr;
    static cudaEvent_t ev0 = nullptr, ev_scan = nullptr, ev_pre = nullptr;
    static cudaEvent_t ev_a0 = nullptr, ev_g2a = nullptr;
    if (!s2) {
        cudaStreamCreateWithFlags(&s2, cudaStreamNonBlocking);
        cudaEventCreateWithFlags(&ev0, cudaEventDisableTiming);
        cudaEventCreateWithFlags(&ev_scan, cudaEventDisableTiming);
        cudaEventCreateWithFlags(&ev_pre, cudaEventDisableTiming);
        cudaEventCreateWithFlags(&ev_a0, cudaEventDisableTiming);
        cudaEventCreateWithFlags(&ev_g2a, cudaEventDisableTiming);
    }

    const int T = 256;
    // chunk boundary for agg_relu/GEMM2 pipelining (multiple of 128)
    const int N2 = ((N / 2 + 127) / 128) * 128;   // 25088 for N=50000

    // ---- fork at t=0: s2 runs weight convert + GEMM1 (graph-independent) ----
    cudaEventRecord(ev0, 0);
    cudaStreamWaitEvent(s2, ev0, 0);
    k_w12h<<<(256 * HID + HID * HID + T - 1) / T, T, 0, s2>>>(W1, Wmu, Wls);
    k_hgemm<false, false><<<(N + 127) / 128, 256, 0, s2>>>(N, 256, 0, x, pW1h, pHs1);

    // ---- main stream: CSR build chain (memset covers scan pad + flags) ----
    cudaMemsetAsync(pdeg, 0, (size_t)(NPAD + 64) * sizeof(int), 0);
    k_hist_rank8<<<(E / 8 + T - 1) / T + 1, T>>>(dst, E);
    k_scan2<<<SCAN_BLOCKS, 1024>>>();
    cudaEventRecord(ev_scan, 0);
    k_scatter8<<<(E / 8 + T - 1) / T + 1, T>>>(src, dst, E);

    // ---- s2: prescale Hs1 by dinv (after GEMM1 + scan), overlaps scatter ----
    cudaStreamWaitEvent(s2, ev_scan, 0);
    k_prescale<<<(N * 32 + T - 1) / T, T, 0, s2>>>(N * 32);
    cudaEventRecord(ev_pre, s2);

    // ---- join, then pipelined tail ----
    cudaStreamWaitEvent(0, ev_pre, 0);
    // agg_relu chunk 0: nodes [0, N2)
    k_agg_relu<<<(N2 * 32 + T - 1) / T, T>>>(0, N2, b1);
    cudaEventRecord(ev_a0, 0);
    // s2: GEMM2 over rows [0, N2) while main runs agg_relu chunk 1
    cudaStreamWaitEvent(s2, ev_a0, 0);
    k_hgemm<true, true><<<N2 / 128, 256, 0, s2>>>(N, 128, 0, phh, pW2h, pHs2);
    cudaEventRecord(ev_g2a, s2);
    // main: agg_relu chunk 1, then GEMM2 over remaining rows
    k_agg_relu<<<((N - N2) * 32 + T - 1) / T, T>>>(N2, N, b1);
    k_hgemm<true, true><<<(N - N2 + 127) / 128, 256>>>(N, 128, N2, phh, pW2h, pHs2);
    cudaStreamWaitEvent(0, ev_g2a, 0);
    k_agg_out<<<(N * 32 + T - 1) / T, T>>>(N, bmu, bls, out);
}

// round 16
// speedup vs baseline: 1.0258x; 1.0258x over previous
#include <cuda_runtime.h>
#include <cuda_fp16.h>
#include <mma.h>
#include <cstdint>

using namespace nvcuda;

// ---------------- problem-size constants (padded maxima for static scratch) ---
constexpr int NMAX = 50048;        // >= 50000 nodes
constexpr int SCAN_BLOCKS = 52;
constexpr int NPAD = SCAN_BLOCKS * 1024;   // 53248 (scan coverage)
constexpr int EMAX = 1600000;      // edges
constexpr int HID  = 128;          // hidden width (both layers use 128 cols)

// ---------------- static device scratch (no allocations allowed) -------------
// g_deg tail [NPAD, NPAD+64) doubles as scan block-sum flags (memset covers it)
__device__ int    g_deg[NPAD + 64];
__device__ float  g_dinv[NPAD];
__device__ int    g_rowstart[NPAD + 4];
__device__ int    g_rank[EMAX];
__device__ int    g_csr_src[EMAX];
__device__ __half g_Hs1[(size_t)NMAX * HID];  // x@W1, then prescaled by dinv (fp16)
__device__ __half g_hh[(size_t)NMAX * HID];   // hidden activations fp16 (GEMM2 A)
__device__ __half g_Hs2[(size_t)NMAX * HID];  // dinv-scaled h@[Wmu|Wls], fp16
__device__ __half g_W1h[256 * HID];           // W1 fp16
__device__ __half g_W2h[HID * HID];           // concat(W_mu, W_ls) fp16

// ---------------- CSR build ---------------------------------------------------
// 8 edges per thread: 8 independent atomic chains for MLP
__global__ void k_hist_rank8(const int* __restrict__ dst, int E) {
    int i = blockIdx.x * blockDim.x + threadIdx.x;
    int base = i * 8;
    if (base + 8 <= E) {
        int4 da = *(const int4*)&dst[base];
        int4 db = *(const int4*)&dst[base + 4];
        int r0 = atomicAdd(&g_deg[da.x], 1);
        int r1 = atomicAdd(&g_deg[da.y], 1);
        int r2 = atomicAdd(&g_deg[da.z], 1);
        int r3 = atomicAdd(&g_deg[da.w], 1);
        int r4 = atomicAdd(&g_deg[db.x], 1);
        int r5 = atomicAdd(&g_deg[db.y], 1);
        int r6 = atomicAdd(&g_deg[db.z], 1);
        int r7 = atomicAdd(&g_deg[db.w], 1);
        *(int4*)&g_rank[base]     = make_int4(r0, r1, r2, r3);
        *(int4*)&g_rank[base + 4] = make_int4(r4, r5, r6, r7);
    } else {
        for (int j = base; j < E; j++) g_rank[j] = atomicAdd(&g_deg[dst[j]], 1);
    }
}

// grid-wide exclusive scan, single pass: 52 blocks x 1024 threads, 1 elem/thread.
__global__ __launch_bounds__(1024) void k_scan2() {
    __shared__ int sh_scan[32];
    __shared__ int sh_red[32];
    __shared__ int s_total, s_off;
    const int b = blockIdx.x, t = threadIdx.x;
    const int idx = b * 1024 + t;
    const int d = g_deg[idx];
    const int lane = t & 31, wid = t >> 5;

    int v = d;
    #pragma unroll
    for (int s = 1; s < 32; s <<= 1) {
        int n = __shfl_up_sync(0xffffffff, v, s);
        if (lane >= s) v += n;
    }
    if (lane == 31) sh_scan[wid] = v;
    __syncthreads();
    if (wid == 0) {
        int w = sh_scan[lane];
        #pragma unroll
        for (int s = 1; s < 32; s <<= 1) {
            int n = __shfl_up_sync(0xffffffff, w, s);
            if (lane >= s) w += n;
        }
        sh_scan[lane] = w;
    }
    __syncthreads();
    int incl = v + (wid > 0 ? sh_scan[wid - 1] : 0);
    int excl = incl - d;
    if (t == 1023) s_total = incl;
    __syncthreads();

    if (t == 0) {
        __threadfence();
        atomicExch(&g_deg[NPAD + b], s_total + 1);
    }

    int p = 0;
    if (t < b) {
        int vv;
        while ((vv = atomicAdd(&g_deg[NPAD + t], 0)) == 0) { __nanosleep(50); }
        p = vv - 1;
    }
    #pragma unroll
    for (int s = 16; s > 0; s >>= 1) p += __shfl_down_sync(0xffffffff, p, s);
    if (lane == 0) sh_red[wid] = p;
    __syncthreads();
    if (wid == 0) {
        int w = sh_red[lane];
        #pragma unroll
        for (int s = 16; s > 0; s >>= 1) w += __shfl_down_sync(0xffffffff, w, s);
        if (lane == 0) s_off = w;
    }
    __syncthreads();

    g_rowstart[idx] = excl + s_off;
    g_dinv[idx] = rsqrtf((float)(d + 1));   // +1 self-loop (pad rows -> 1, unused)
}

// 8 edges per thread: 8 independent load->load->store chains
__global__ void k_scatter8(const int* __restrict__ src, const int* __restrict__ dst, int E) {
    int i = blockIdx.x * blockDim.x + threadIdx.x;
    int base = i * 8;
    if (base + 8 <= E) {
        int4 da = *(const int4*)&dst[base];
        int4 db = *(const int4*)&dst[base + 4];
        int4 ra = *(const int4*)&g_rank[base];
        int4 rb = *(const int4*)&g_rank[base + 4];
        int4 sa = *(const int4*)&src[base];
        int4 sb = *(const int4*)&src[base + 4];
        int p0 = g_rowstart[da.x] + ra.x;
        int p1 = g_rowstart[da.y] + ra.y;
        int p2 = g_rowstart[da.z] + ra.z;
        int p3 = g_rowstart[da.w] + ra.w;
        int p4 = g_rowstart[db.x] + rb.x;
        int p5 = g_rowstart[db.y] + rb.y;
        int p6 = g_rowstart[db.z] + rb.z;
        int p7 = g_rowstart[db.w] + rb.w;
        g_csr_src[p0] = sa.x;
        g_csr_src[p1] = sa.y;
        g_csr_src[p2] = sa.z;
        g_csr_src[p3] = sa.w;
        g_csr_src[p4] = sb.x;
        g_csr_src[p5] = sb.y;
        g_csr_src[p6] = sb.z;
        g_csr_src[p7] = sb.w;
    } else {
        for (int j = base; j < E; j++)
            g_csr_src[g_rowstart[dst[j]] + g_rank[j]] = src[j];
    }
}

// fused weight conversion: W1 (256x128) and [Wmu|Wls] (128x128) to fp16
__global__ void k_w12h(const float* __restrict__ W1, const float* __restrict__ Wmu,
                       const float* __restrict__ Wls) {
    int i = blockIdx.x * blockDim.x + threadIdx.x;
    if (i < 256 * HID) {
        g_W1h[i] = __float2half_rn(W1[i]);
    } else if (i < 256 * HID + HID * HID) {
        int j = i - 256 * HID;
        int k = j >> 7, c = j & 127;
        g_W2h[j] = __float2half_rn((c < 64) ? Wmu[k * 64 + c] : Wls[k * 64 + (c - 64)]);
    }
}

// in-place row prescale: Hs1[r,:] *= dinv[r]  (uint2 = 4 halves per thread)
__global__ void k_prescale(int total) {
    int i = blockIdx.x * blockDim.x + threadIdx.x;
    if (i >= total) return;
    int row = i >> 5;                         // warp-uniform
    float w = g_dinv[row];
    uint2 u = ((const uint2*)g_Hs1)[i];
    float2 lo = __half22float2(*reinterpret_cast<__half2*>(&u.x));
    float2 hi = __half22float2(*reinterpret_cast<__half2*>(&u.y));
    __half2 h0 = __float22half2_rn(make_float2(lo.x * w, lo.y * w));
    __half2 h1 = __float22half2_rn(make_float2(hi.x * w, hi.y * w));
    uint2 o;
    o.x = *reinterpret_cast<unsigned*>(&h0);
    o.y = *reinterpret_cast<unsigned*>(&h1);
    ((uint2*)g_Hs1)[i] = o;
}

// ---------------- helpers ------------------------------------------------------
__device__ __forceinline__ void acc_h4(float4& a, uint2 u) {
    float2 lo = __half22float2(*reinterpret_cast<__half2*>(&u.x));
    float2 hi = __half22float2(*reinterpret_cast<__half2*>(&u.y));
    a.x += lo.x; a.y += lo.y; a.z += hi.x; a.w += hi.y;
}

// unweighted gather-sum (rows already dinv-prescaled); MLP-16 main loop
__device__ __forceinline__ float4 gather_sum(const uint2* __restrict__ Hs4,
                                             int node, int lane) {
    uint2 self = Hs4[(size_t)node * 32 + lane];
    float4 acc = make_float4(0.f, 0.f, 0.f, 0.f);
    acc_h4(acc, self);

    int e = g_rowstart[node];
    const int end = g_rowstart[node + 1];
    for (; e + 16 <= end; e += 16) {
        int s0 = g_csr_src[e + 0],  s1 = g_csr_src[e + 1];
        int s2 = g_csr_src[e + 2],  s3 = g_csr_src[e + 3];
        int s4 = g_csr_src[e + 4],  s5 = g_csr_src[e + 5];
        int s6 = g_csr_src[e + 6],  s7 = g_csr_src[e + 7];
        int s8 = g_csr_src[e + 8],  s9 = g_csr_src[e + 9];
        int sa = g_csr_src[e + 10], sb = g_csr_src[e + 11];
        int sc = g_csr_src[e + 12], sd = g_csr_src[e + 13];
        int se = g_csr_src[e + 14], sf = g_csr_src[e + 15];
        uint2 u0 = __ldg(&Hs4[(size_t)s0 * 32 + lane]);
        uint2 u1 = __ldg(&Hs4[(size_t)s1 * 32 + lane]);
        uint2 u2 = __ldg(&Hs4[(size_t)s2 * 32 + lane]);
        uint2 u3 = __ldg(&Hs4[(size_t)s3 * 32 + lane]);
        uint2 u4 = __ldg(&Hs4[(size_t)s4 * 32 + lane]);
        uint2 u5 = __ldg(&Hs4[(size_t)s5 * 32 + lane]);
        uint2 u6 = __ldg(&Hs4[(size_t)s6 * 32 + lane]);
        uint2 u7 = __ldg(&Hs4[(size_t)s7 * 32 + lane]);
        uint2 u8 = __ldg(&Hs4[(size_t)s8 * 32 + lane]);
        uint2 u9 = __ldg(&Hs4[(size_t)s9 * 32 + lane]);
        uint2 ua = __ldg(&Hs4[(size_t)sa * 32 + lane]);
        uint2 ub = __ldg(&Hs4[(size_t)sb * 32 + lane]);
        uint2 uc = __ldg(&Hs4[(size_t)sc * 32 + lane]);
        uint2 ud = __ldg(&Hs4[(size_t)sd * 32 + lane]);
        uint2 ue = __ldg(&Hs4[(size_t)se * 32 + lane]);
        uint2 uf = __ldg(&Hs4[(size_t)sf * 32 + lane]);
        acc_h4(acc, u0); acc_h4(acc, u1); acc_h4(acc, u2); acc_h4(acc, u3);
        acc_h4(acc, u4); acc_h4(acc, u5); acc_h4(acc, u6); acc_h4(acc, u7);
        acc_h4(acc, u8); acc_h4(acc, u9); acc_h4(acc, ua); acc_h4(acc, ub);
        acc_h4(acc, uc); acc_h4(acc, ud); acc_h4(acc, ue); acc_h4(acc, uf);
    }
    for (; e + 8 <= end; e += 8) {
        int s0 = g_csr_src[e + 0], s1 = g_csr_src[e + 1];
        int s2 = g_csr_src[e + 2], s3 = g_csr_src[e + 3];
        int s4 = g_csr_src[e + 4], s5 = g_csr_src[e + 5];
        int s6 = g_csr_src[e + 6], s7 = g_csr_src[e + 7];
        uint2 u0 = __ldg(&Hs4[(size_t)s0 * 32 + lane]);
        uint2 u1 = __ldg(&Hs4[(size_t)s1 * 32 + lane]);
        uint2 u2 = __ldg(&Hs4[(size_t)s2 * 32 + lane]);
        uint2 u3 = __ldg(&Hs4[(size_t)s3 * 32 + lane]);
        uint2 u4 = __ldg(&Hs4[(size_t)s4 * 32 + lane]);
        uint2 u5 = __ldg(&Hs4[(size_t)s5 * 32 + lane]);
        uint2 u6 = __ldg(&Hs4[(size_t)s6 * 32 + lane]);
        uint2 u7 = __ldg(&Hs4[(size_t)s7 * 32 + lane]);
        acc_h4(acc, u0); acc_h4(acc, u1); acc_h4(acc, u2); acc_h4(acc, u3);
        acc_h4(acc, u4); acc_h4(acc, u5); acc_h4(acc, u6); acc_h4(acc, u7);
    }
    for (; e + 2 <= end; e += 2) {
        int s0 = g_csr_src[e + 0], s1 = g_csr_src[e + 1];
        uint2 u0 = __ldg(&Hs4[(size_t)s0 * 32 + lane]);
        uint2 u1 = __ldg(&Hs4[(size_t)s1 * 32 + lane]);
        acc_h4(acc, u0); acc_h4(acc, u1);
    }
    if (e < end) {
        uint2 u = __ldg(&Hs4[(size_t)g_csr_src[e] * 32 + lane]);
        acc_h4(acc, u);
    }
    return acc;
}

// ---------------- aggregation, one warp per node -------------------------------
// P[d,:] = dinv[d] * ( Hs[d,:] + sum_{edges s->d} Hs[s,:] )   (Hs prescaled)
// layer 1 variant: h = relu(P + b1), write fp16 (feeds tensor-core GEMM2)
__global__ __launch_bounds__(256) void k_agg_relu(int N, const float* __restrict__ b) {
    int warp = (blockIdx.x * blockDim.x + threadIdx.x) >> 5;
    int lane = threadIdx.x & 31;
    if (warp >= N) return;
    float4 acc = gather_sum((const uint2*)g_Hs1, warp, lane);

    float dd = g_dinv[warp];
    int c = lane * 4;
    float4 bb = *(const float4*)&b[c];
    __half2 h0 = __float22half2_rn(make_float2(fmaxf(acc.x * dd + bb.x, 0.f),
                                               fmaxf(acc.y * dd + bb.y, 0.f)));
    __half2 h1 = __float22half2_rn(make_float2(fmaxf(acc.z * dd + bb.z, 0.f),
                                               fmaxf(acc.w * dd + bb.w, 0.f)));
    uint2 pack;
    pack.x = *reinterpret_cast<unsigned*>(&h0);
    pack.y = *reinterpret_cast<unsigned*>(&h1);
    ((uint2*)g_hh)[(size_t)warp * 32 + lane] = pack;
}

// layer 2 variant: split into (mu, logstd) halves with biases, write to output
__global__ __launch_bounds__(256) void k_agg_out(int N, const float* __restrict__ bmu,
                                                 const float* __restrict__ bls,
                                                 float* __restrict__ out) {
    int warp = (blockIdx.x * blockDim.x + threadIdx.x) >> 5;
    int lane = threadIdx.x & 31;
    if (warp >= N) return;
    float4 acc = gather_sum((const uint2*)g_Hs2, warp, lane);

    float dd = g_dinv[warp];
    int c = lane * 4;   // 0..124
    float4 r;
    if (c < 64) {
        float4 bb = *(const float4*)&bmu[c];
        r.x = acc.x * dd + bb.x; r.y = acc.y * dd + bb.y;
        r.z = acc.z * dd + bb.z; r.w = acc.w * dd + bb.w;
        *(float4*)&out[(size_t)warp * 64 + c] = r;
    } else {
        float4 bb = *(const float4*)&bls[c - 64];
        r.x = acc.x * dd + bb.x; r.y = acc.y * dd + bb.y;
        r.z = acc.z * dd + bb.z; r.w = acc.w * dd + bb.w;
        *(float4*)&out[(size_t)N * 64 + (size_t)warp * 64 + (c - 64)] = r;
    }
}

// ---------------- tensor-core GEMM: Hs[M,128] = fp16([dinv[m]*](A[M,K]@B[K,128]))
// BM=128, BN=128, BK=32. 256 threads = 8 warps in 4x2 grid; warp tile 32x64.
template<bool A_IS_HALF, bool SCALE_D>
__global__ __launch_bounds__(256) void k_hgemm(int M, int K,
                                               const void* __restrict__ Av,
                                               const __half* __restrict__ B,
                                               __half* __restrict__ Hs) {
    constexpr int BM = 128, BN = 128, BK = 32;
    __shared__ __align__(32) __half As[BM][BK + 8];
    __shared__ __align__(32) __half Bs[BK][BN + 8];
    __shared__ __align__(32) float  Cs[8][16][24];

    const int tid = threadIdx.x;
    const int wid = tid >> 5;
    const int lane = tid & 31;
    const int warp_m = wid >> 1;          // 0..3
    const int warp_n = wid & 1;           // 0..1
    const int block_row = blockIdx.x * BM;

    wmma::fragment<wmma::accumulator, 16, 16, 16, float> facc[2][4];
    #pragma unroll
    for (int i = 0; i < 2; i++)
        #pragma unroll
        for (int j = 0; j < 4; j++) wmma::fill_fragment(facc[i][j], 0.0f);

    for (int k0 = 0; k0 < K; k0 += BK) {
        if (A_IS_HALF) {
            const __half* A = (const __half*)Av;
            #pragma unroll
            for (int i = 0; i < 4; i++) {
                int idx = tid + i * 256;
                int r = idx >> 3, c4 = (idx & 7) * 4;
                int gr = block_row + r;
                uint2 v = make_uint2(0u, 0u);
                if (gr < M) v = *(const uint2*)&A[(size_t)gr * K + k0 + c4];
                *(uint2*)&As[r][c4] = v;
            }
        } else {
            const float* A = (const float*)Av;
            #pragma unroll
            for (int i = 0; i < 4; i++) {
                int idx = tid + i * 256;
                int r = idx >> 3, c4 = (idx & 7) * 4;
                int gr = block_row + r;
                float4 v = make_float4(0.f, 0.f, 0.f, 0.f);
                if (gr < M) v = *(const float4*)&A[(size_t)gr * K + k0 + c4];
                __half2 h0 = __float22half2_rn(make_float2(v.x, v.y));
                __half2 h1 = __float22half2_rn(make_float2(v.z, v.w));
                uint2 pack;
                pack.x = *reinterpret_cast<unsigned*>(&h0);
                pack.y = *reinterpret_cast<unsigned*>(&h1);
                *(uint2*)&As[r][c4] = pack;
            }
        }
        #pragma unroll
        for (int i = 0; i < 4; i++) {
            int idx = tid + i * 256;
            int r = idx >> 5, c4 = (idx & 31) * 4;
            *(uint2*)&Bs[r][c4] = *(const uint2*)&B[(size_t)(k0 + r) * BN + c4];
        }
        __syncthreads();

        #pragma unroll
        for (int kk = 0; kk < BK; kk += 16) {
            wmma::fragment<wmma::matrix_a, 16, 16, 16, __half, wmma::row_major> fa[2];
            wmma::fragment<wmma::matrix_b, 16, 16, 16, __half, wmma::row_major> fb[4];
            #pragma unroll
            for (int i = 0; i < 2; i++)
                wmma::load_matrix_sync(fa[i], &As[warp_m * 32 + i * 16][kk], BK + 8);
            #pragma unroll
            for (int j = 0; j < 4; j++)
                wmma::load_matrix_sync(fb[j], &Bs[kk][warp_n * 64 + j * 16], BN + 8);
            #pragma unroll
            for (int i = 0; i < 2; i++)
                #pragma unroll
                for (int j = 0; j < 4; j++)
                    wmma::mma_sync(facc[i][j], fa[i], fb[j], facc[i][j]);
        }
        __syncthreads();
    }

    // ---- epilogue: optional row scale by dinv, convert fp16, store ----
    #pragma unroll
    for (int i = 0; i < 2; i++) {
        #pragma unroll
        for (int j = 0; j < 4; j++) {
            wmma::store_matrix_sync(&Cs[wid][0][0], facc[i][j], 24, wmma::mem_row_major);
            __syncwarp();
            int r = lane >> 1;
            int gr = block_row + warp_m * 32 + i * 16 + r;
            int col = warp_n * 64 + j * 16 + (lane & 1) * 8;
            if (gr < M) {
                float di = SCALE_D ? g_dinv[gr] : 1.0f;
                float4 v0 = *(float4*)&Cs[wid][r][(lane & 1) * 8];
                float4 v1 = *(float4*)&Cs[wid][r][(lane & 1) * 8 + 4];
                __half2 h0 = __float22half2_rn(make_float2(v0.x * di, v0.y * di));
                __half2 h1 = __float22half2_rn(make_float2(v0.z * di, v0.w * di));
                __half2 h2 = __float22half2_rn(make_float2(v1.x * di, v1.y * di));
                __half2 h3 = __float22half2_rn(make_float2(v1.z * di, v1.w * di));
                uint4 pack;
                pack.x = *reinterpret_cast<unsigned*>(&h0);
                pack.y = *reinterpret_cast<unsigned*>(&h1);
                pack.z = *reinterpret_cast<unsigned*>(&h2);
                pack.w = *reinterpret_cast<unsigned*>(&h3);
                *(uint4*)&Hs[(size_t)gr * BN + col] = pack;
            }
            __syncwarp();
        }
    }
}

// ---------------- launch ------------------------------------------------------
extern "C" void kernel_launch(void* const* d_in, const int* in_sizes, int n_in,
                              void* d_out, int out_size) {
    const float* x  = (const float*)d_in[0];
    const int*   ei = (const int*)d_in[1];
    int base = (n_in >= 9 && in_sizes[2] == 1) ? 3 : 2;
    const float* W1  = (const float*)d_in[base + 0];
    const float* b1  = (const float*)d_in[base + 1];
    const float* Wmu = (const float*)d_in[base + 2];
    const float* bmu = (const float*)d_in[base + 3];
    const float* Wls = (const float*)d_in[base + 4];
    const float* bls = (const float*)d_in[base + 5];
    float* out = (float*)d_out;

    const int N = in_sizes[0] / 256;   // 50000
    const int E = in_sizes[1] / 2;     // 1600000
    const int* src = ei;
    const int* dst = ei + E;

    __half *pHs1, *pHs2, *phh, *pW1h, *pW2h;
    int* pdeg;
    cudaGetSymbolAddress((void**)&pHs1, g_Hs1);
    cudaGetSymbolAddress((void**)&phh,  g_hh);
    cudaGetSymbolAddress((void**)&pHs2, g_Hs2);
    cudaGetSymbolAddress((void**)&pW1h, g_W1h);
    cudaGetSymbolAddress((void**)&pW2h, g_W2h);
    cudaGetSymbolAddress((void**)&pdeg, g_deg);

    // one-time side-stream + events (host resources, not device memory)
    static cudaStream_t s2 = nullptr;
    static cudaEvent_t ev0 = nullptr, ev_scan = nullptr, ev_pre = nullptr;
    if (!s2) {
        cudaStreamCreateWithFlags(&s2, cudaStreamNonBlocking);
        cudaEventCreateWithFlags(&ev0, cudaEventDisableTiming);
        cudaEventCreateWithFlags(&ev_scan, cudaEventDisableTiming);
        cudaEventCreateWithFlags(&ev_pre, cudaEventDisableTiming);
    }

    const int T = 256;
    // ---- fork at t=0: s2 runs weight convert + GEMM1 (graph-independent) ----
    cudaEventRecord(ev0, 0);
    cudaStreamWaitEvent(s2, ev0, 0);
    k_w12h<<<(256 * HID + HID * HID + T - 1) / T, T, 0, s2>>>(W1, Wmu, Wls);
    k_hgemm<false, false><<<(N + 127) / 128, 256, 0, s2>>>(N, 256, x, pW1h, pHs1);

    // ---- main stream: CSR build chain (memset covers scan pad + flags) ----
    cudaMemsetAsync(pdeg, 0, (size_t)(NPAD + 64) * sizeof(int), 0);
    k_hist_rank8<<<(E / 8 + T - 1) / T + 1, T>>>(dst, E);
    k_scan2<<<SCAN_BLOCKS, 1024>>>();
    cudaEventRecord(ev_scan, 0);
    k_scatter8<<<(E / 8 + T - 1) / T + 1, T>>>(src, dst, E);

    // ---- s2: prescale Hs1 by dinv (after GEMM1 + scan), overlaps scatter ----
    cudaStreamWaitEvent(s2, ev_scan, 0);
    k_prescale<<<(N * 32 + T - 1) / T, T, 0, s2>>>(N * 32);
    cudaEventRecord(ev_pre, s2);

    // ---- join, then the serial tail ----
    cudaStreamWaitEvent(0, ev_pre, 0);
    k_agg_relu<<<(N * 32 + T - 1) / T, T>>>(N, b1);
    k_hgemm<true, true><<<(N + 127) / 128, 256>>>(N, 128, phh, pW2h, pHs2);
    k_agg_out<<<(N * 32 + T - 1) / T, T>>>(N, bmu, bls, out);
}